// round 15
// baseline (speedup 1.0000x reference)
#include <cuda_runtime.h>
#include <cuda_fp16.h>
#include <cstdint>

// ============================================================================
// HGCN (2-layer hyperbolic GCN), c = 1.
//
// R15 pipeline (= R14 + MLP-unrolled gather):
//   main stream:  prep(W->fp16, hb1, hb2) -> mmaGEMM<0>(x,W1) -> kA1 ->
//                 [join csr] gather1 -> mmaGEMM<1>(h1,W2) -> kA2 -> gather2
//   side stream:  zero_cur -> fill (atomic cursor into dst*MAXDEG buckets)
//
// GEMM: A,W rounded to fp16, fp32 accumulate (xn from exact fp32 row norms).
// Gather: batched inner loop (8 edges in flight) to hide L2 latency.
// xt stored fp16. Edge buckets padded to MAXDEG=96.
// ============================================================================

#define BALL_MAXN 0.996f     // (1 - 4e-3)/sqrt(c)
#define EPSN      1e-15f
#define NODES_MAX 80000
#define MAXDEG    96
#define DIM       64

__device__ float  d_g  [NODES_MAX * DIM];
__device__ __half d_xt [NODES_MAX * DIM];
__device__ float  d_h1 [NODES_MAX * DIM];
__device__ float  d_xn [NODES_MAX];
__device__ float  d_hb1[65];
__device__ float  d_hb2[65];
__device__ int    d_cur[NODES_MAX];
__device__ int2   d_edata[(size_t)NODES_MAX * MAXDEG];
__device__ unsigned d_wh1[64 * 256 / 2];   // W1 as packed half2 pairs along K
__device__ unsigned d_wh2[64 * 64 / 2];    // W2 as packed half2 pairs along K

__device__ __forceinline__ float wsum(float v) {
#pragma unroll
    for (int o = 16; o; o >>= 1) v += __shfl_xor_sync(0xffffffffu, v, o);
    return v;
}

__device__ __forceinline__ float artanh_f(float x) {
    x = fminf(fmaxf(x, -1.0f + 1e-7f), 1.0f - 1e-7f);
    return 0.5f * logf((1.0f + x) / (1.0f - x));
}

// pack two fp32 into one half2 (lo half = f0)
__device__ __forceinline__ unsigned pack_h2(float f0, float f1) {
    unsigned h;
    asm("cvt.rn.f16x2.f32 %0, %1, %2;" : "=r"(h) : "f"(f1), "f"(f0));
    return h;
}

#define MMA_FP16(d, a0, a1, a2, a3, b0, b1) \
    asm volatile("mma.sync.aligned.m16n8k16.row.col.f32.f16.f16.f32 " \
        "{%0,%1,%2,%3}, {%4,%5,%6,%7}, {%8,%9}, {%0,%1,%2,%3};" \
        : "+f"((d)[0]), "+f"((d)[1]), "+f"((d)[2]), "+f"((d)[3]) \
        : "r"(a0), "r"(a1), "r"(a2), "r"(a3), "r"(b0), "r"(b1))

// ---------------------------------------------------------------------------
// hb = proj(expmap0(b)); hb[64] = ||hb||^2.  Runs inside a 256-thread block.
// ---------------------------------------------------------------------------
__device__ void hb_dev(const float* __restrict__ b, float* __restrict__ hb) {
    __shared__ float sm[2];
    int t = threadIdx.x;
    float v = (t < 64) ? b[t] : 0.0f;
    float ss = wsum(v * v);
    if (t < 64 && (t & 31) == 0) sm[t >> 5] = ss;
    __syncthreads();
    float tot = sm[0] + sm[1];
    __syncthreads();
    float nr = sqrtf(tot);
    float n  = fmaxf(nr, EPSN);
    float tn = tanhf(n);
    float e  = v * (tn / n);
    float en = fmaxf(tn * (nr / n), EPSN);
    float cf = (en > BALL_MAXN) ? (BALL_MAXN / en) : 1.0f;
    e *= cf;
    if (t < 64) hb[t] = e;
    float ss2 = wsum((t < 64) ? e * e : 0.0f);
    if (t < 64 && (t & 31) == 0) sm[t >> 5] = ss2;
    __syncthreads();
    if (t == 0) hb[64] = sm[0] + sm[1];
}

// ---------------------------------------------------------------------------
// prep: block 0 -> hb1, block 1 -> hb2, blocks 2.. -> W1/W2 fp16 pack.
// ---------------------------------------------------------------------------
#define W1_PAIRS (64 * 256 / 2)
#define W2_PAIRS (64 * 64 / 2)

__global__ void prep_kernel(const float* __restrict__ W1, unsigned* __restrict__ wh1,
                            const float* __restrict__ W2, unsigned* __restrict__ wh2,
                            const float* __restrict__ b1, float* __restrict__ hb1,
                            const float* __restrict__ b2, float* __restrict__ hb2) {
    int blk = blockIdx.x;
    if (blk == 0) { hb_dev(b1, hb1); return; }
    if (blk == 1) { hb_dev(b2, hb2); return; }
    int i = (blk - 2) * 256 + threadIdx.x;
    if (i < W1_PAIRS) {
        float2 f = ((const float2*)W1)[i];
        wh1[i] = pack_h2(f.x, f.y);
    } else if (i < W1_PAIRS + W2_PAIRS) {
        int j = i - W1_PAIRS;
        float2 f = ((const float2*)W2)[j];
        wh2[j] = pack_h2(f.x, f.y);
    }
}

// ---------------------------------------------------------------------------
// Scan-free CSR: zero cursors, then bucket-fill edata[dst*MAXDEG + pos].
// ---------------------------------------------------------------------------
__global__ void zero_cur_kernel(int* __restrict__ cur, int N) {
    int i = blockIdx.x * blockDim.x + threadIdx.x;
    if (i < N) cur[i] = 0;
}

__global__ void fill_kernel(const int* __restrict__ src, const int* __restrict__ dst,
                            const float* __restrict__ w, int* __restrict__ cur,
                            int2* __restrict__ ed, int E) {
    int e = blockIdx.x * blockDim.x + threadIdx.x;
    if (e >= E) return;
    int d = dst[e];
    int pos = atomicAdd(&cur[d], 1);
    if (pos < MAXDEG)
        ed[(size_t)d * MAXDEG + pos] = make_int2(src[e], __float_as_int(w[e]));
}

// ---------------------------------------------------------------------------
// Pipelined fp16 tensor-core GEMM: C[N,64] = A[N,K] @ W[64,K]^T.
// Tile M=128, N=64, BK=32; 8 warps 4(m) x 2(n); 2 mt x 4 nt per warp.
// Register prefetch of next slab overlaps MMAs; double-buffered smem.
// MODE 0: fused encode scale (from exact fp32 row norms) + xn out.
// ---------------------------------------------------------------------------
#define BM 128
#define KPAD 17

template <int MODE, int K>
__global__ __launch_bounds__(256, 2)
void gemm_mma_kernel(const float* __restrict__ A,
                     const unsigned* __restrict__ wh,
                     float* __restrict__ C, float* __restrict__ xn_io, int N) {
    __shared__ unsigned Ah[2][BM * KPAD];
    __shared__ float sred[4 * 256];
    __shared__ float ssc[BM];

    int tid  = threadIdx.x;
    int lane = tid & 31;
    int wid  = tid >> 5;
    int warp_m = wid >> 1;
    int warp_n = wid & 1;
    int block_row = blockIdx.x * BM;

    int qrow = lane >> 2;
    int qcol = lane & 3;

    float acc[2][4][4];
#pragma unroll
    for (int mt = 0; mt < 2; mt++)
#pragma unroll
        for (int nt = 0; nt < 4; nt++)
#pragma unroll
            for (int r = 0; r < 4; r++) acc[mt][nt][r] = 0.0f;

    float ssl[4] = {0.f, 0.f, 0.f, 0.f};

    int rr[4], kb[4];
    const float* aptr[4];
#pragma unroll
    for (int i = 0; i < 4; i++) {
        int idx = tid + i * 256;
        rr[i] = idx >> 3;
        kb[i] = ((idx & 7) << 2) >> 1;
        int gr = block_row + rr[i];
        if (gr >= N) gr = N - 1;
        aptr[i] = A + (size_t)gr * K + ((idx & 7) << 2);
    }

    float4 rv[4];
#pragma unroll
    for (int i = 0; i < 4; i++) rv[i] = *(const float4*)(aptr[i]);

    const int S = K / 32;
#pragma unroll 1
    for (int s = 0; s < S; s++) {
        int buf = s & 1;
#pragma unroll
        for (int i = 0; i < 4; i++) {
            int base = rr[i] * KPAD + kb[i];
            Ah[buf][base]     = pack_h2(rv[i].x, rv[i].y);
            Ah[buf][base + 1] = pack_h2(rv[i].z, rv[i].w);
            if (MODE == 0)
                ssl[i] += rv[i].x * rv[i].x + rv[i].y * rv[i].y
                        + rv[i].z * rv[i].z + rv[i].w * rv[i].w;
        }
        __syncthreads();

        if (s + 1 < S) {
#pragma unroll
            for (int i = 0; i < 4; i++)
                rv[i] = *(const float4*)(aptr[i] + (s + 1) * 32);
        }

#pragma unroll
        for (int kc = 0; kc < 2; kc++) {
            int pc = kc * 8 + qcol;
            unsigned ah[2][4];
#pragma unroll
            for (int mt = 0; mt < 2; mt++) {
                int r0 = warp_m * 32 + mt * 16 + qrow;
                ah[mt][0] = Ah[buf][r0 * KPAD + pc];
                ah[mt][1] = Ah[buf][(r0 + 8) * KPAD + pc];
                ah[mt][2] = Ah[buf][r0 * KPAD + pc + 4];
                ah[mt][3] = Ah[buf][(r0 + 8) * KPAD + pc + 4];
            }
#pragma unroll
            for (int nt = 0; nt < 4; nt++) {
                int n  = warp_n * 32 + nt * 8 + qrow;
                int kp = (s * 32 + kc * 16) / 2 + qcol;
                int bidx = n * (K / 2) + kp;
                unsigned b0 = __ldg(&wh[bidx]);
                unsigned b1 = __ldg(&wh[bidx + 4]);
#pragma unroll
                for (int mt = 0; mt < 2; mt++)
                    MMA_FP16(acc[mt][nt], ah[mt][0], ah[mt][1], ah[mt][2], ah[mt][3], b0, b1);
            }
        }
    }

    if (MODE == 0) {
        sred[0 * 256 + tid] = ssl[0];
        sred[1 * 256 + tid] = ssl[1];
        sred[2 * 256 + tid] = ssl[2];
        sred[3 * 256 + tid] = ssl[3];
        __syncthreads();
        if (tid < 128) {
            int r   = tid;
            int grp = r >> 5;
            int t0  = (r & 31) << 3;
            float s2 = 0.0f;
#pragma unroll
            for (int j = 0; j < 8; j++) s2 += sred[grp * 256 + t0 + j];
            float nxr = sqrtf(s2);
            float nx  = fmaxf(nxr, EPSN);
            float t   = tanhf(nx);
            float en  = fmaxf(t * (nxr / nx), EPSN);
            float cf  = (en > BALL_MAXN) ? (BALL_MAXN / en) : 1.0f;
            ssc[r] = (t / nx) * cf;
            int gr = block_row + r;
            if (gr < N) xn_io[gr] = fmaxf(en * cf, EPSN);
        }
        __syncthreads();
    }

#pragma unroll
    for (int mt = 0; mt < 2; mt++) {
#pragma unroll
        for (int nt = 0; nt < 4; nt++) {
            int r0 = warp_m * 32 + mt * 16 + qrow;
            int c  = warp_n * 32 + nt * 8 + qcol * 2;
            int gr0 = block_row + r0;
            int gr1 = gr0 + 8;
            if (gr0 < N) {
                float sc = (MODE == 0) ? ssc[r0] : 1.0f;
                float2 o = make_float2(acc[mt][nt][0] * sc, acc[mt][nt][1] * sc);
                *(float2*)(C + (size_t)gr0 * DIM + c) = o;
            }
            if (gr1 < N) {
                float sc = (MODE == 0) ? ssc[r0 + 8] : 1.0f;
                float2 o = make_float2(acc[mt][nt][2] * sc, acc[mt][nt][3] * sc);
                *(float2*)(C + (size_t)gr1 * DIM + c) = o;
            }
        }
    }
}

// ---------------------------------------------------------------------------
// kA: mv = proj(mobius_matvec tail); h = proj(mobius_add(mv, hb)); xt = logmap0.
// Warp per row, 2 dims per lane. Output stored fp16 (math all fp32).
// ---------------------------------------------------------------------------
__global__ void kA_kernel(const float* __restrict__ g,
                          const float* __restrict__ xnarr,
                          const float* __restrict__ hb,
                          __half* __restrict__ xt_out, int N) {
    int row  = blockIdx.x * 8 + (threadIdx.x >> 5);
    int lane = threadIdx.x & 31;
    if (row >= N) return;

    float2 mx = *(const float2*)(g + (size_t)row * DIM + lane * 2);
    float xn = xnarr[row];

    float mxn2 = wsum(mx.x * mx.x + mx.y * mx.y);
    float mxnr = sqrtf(mxn2);
    float mxn  = fmaxf(mxnr, EPSN);
    float tv   = tanhf(mxn / xn * artanh_f(xn));
    float rs   = tv / mxn;
    float rx = mx.x * rs, ry = mx.y * rs;

    float rn = fmaxf(mxnr * fabsf(rs), EPSN);
    if (rn > BALL_MAXN) { float f = BALL_MAXN / rn; rx *= f; ry *= f; }

    float hbx = hb[lane * 2], hby = hb[lane * 2 + 1];
    float y2  = hb[64];
    float x2  = wsum(rx * rx + ry * ry);
    float xy  = wsum(rx * hbx + ry * hby);
    float den = fmaxf(1.0f + 2.0f * xy + x2 * y2, EPSN);
    float ca  = (1.0f + 2.0f * xy + y2) / den;
    float cb  = (1.0f - x2) / den;
    float hx = ca * rx + cb * hbx;
    float hy = ca * ry + cb * hby;

    float hn2 = wsum(hx * hx + hy * hy);
    float hnr = sqrtf(hn2);
    float hn  = fmaxf(hnr, EPSN);
    float cf2 = (hn > BALL_MAXN) ? (BALL_MAXN / hn) : 1.0f;
    hx *= cf2; hy *= cf2;

    float hna = fmaxf(hnr * cf2, EPSN);
    float lc  = artanh_f(hna) / hna;
    __half2 o = __floats2half2_rn(hx * lc, hy * lc);
    *(__half2*)(xt_out + (size_t)row * DIM + lane * 2) = o;
}

// ---------------------------------------------------------------------------
// Gather + kC over padded buckets, MLP-unrolled: 8 edges in flight.
// Padding lanes carry (src=0, w=0) so the unrolled body is branch-free.
// ---------------------------------------------------------------------------
__global__ void gather_kc_kernel(const __half* __restrict__ xt,
                                 const int2* __restrict__ ed,
                                 const int* __restrict__ deg,
                                 float* __restrict__ out,
                                 float* __restrict__ xn_out, int N) {
    int row  = blockIdx.x * 8 + (threadIdx.x >> 5);
    int lane = threadIdx.x & 31;
    if (row >= N) return;

    size_t beg = (size_t)row * MAXDEG;
    int dc = min(deg[row], MAXDEG);

    float ax = 0.0f, ay = 0.0f;
    for (int i0 = 0; i0 < dc; i0 += 32) {
        int i = i0 + lane;
        int2 e = make_int2(0, 0);          // src=0 (valid addr), w=0
        if (i < dc) e = __ldg(&ed[beg + i]);
        int cnt = min(32, dc - i0);
        for (int j0 = 0; j0 < cnt; j0 += 8) {
            float wt[8];
            const __half2* p[8];
#pragma unroll
            for (int j = 0; j < 8; j++) {
                int jj = (j0 + j) & 31;
                int   s  = __shfl_sync(0xffffffffu, e.x, jj);
                float w_ = __int_as_float(__shfl_sync(0xffffffffu, e.y, jj));
                wt[j] = w_;                 // lanes beyond dc carry w=0
                p[j]  = (const __half2*)(xt + (size_t)s * DIM + lane * 2);
            }
            __half2 v[8];
#pragma unroll
            for (int j = 0; j < 8; j++) v[j] = __ldg(p[j]);
#pragma unroll
            for (int j = 0; j < 8; j++) {
                float2 f = __half22float2(v[j]);
                ax = fmaf(wt[j], f.x, ax);
                ay = fmaf(wt[j], f.y, ay);
            }
        }
    }

    float na2 = wsum(ax * ax + ay * ay);
    float nar = sqrtf(na2);
    float na  = fmaxf(nar, EPSN);
    float t   = tanhf(na);
    float f1  = t / na;
    float en  = fmaxf(t * (nar / na), EPSN);
    float c1  = (en > BALL_MAXN) ? (BALL_MAXN / en) : 1.0f;
    float hn  = fmaxf(en * c1, EPSN);
    float lco = artanh_f(hn) / hn * (f1 * c1);

    float lx = fmaxf(ax * lco, 0.0f);
    float ly = fmaxf(ay * lco, 0.0f);

    float nx2 = wsum(lx * lx + ly * ly);
    float nxr = sqrtf(nx2);
    float nx  = fmaxf(nxr, EPSN);
    float t2  = tanhf(nx);
    float f2  = t2 / nx;
    float en2 = fmaxf(t2 * (nxr / nx), EPSN);
    float c2  = (en2 > BALL_MAXN) ? (BALL_MAXN / en2) : 1.0f;

    float2 o = make_float2(lx * (f2 * c2), ly * (f2 * c2));
    *(float2*)(out + (size_t)row * DIM + lane * 2) = o;

    if (xn_out != nullptr && lane == 0)
        xn_out[row] = fmaxf(en2 * c2, EPSN);
}

// ---------------------------------------------------------------------------
// Launch
// ---------------------------------------------------------------------------
extern "C" void kernel_launch(void* const* d_in, const int* in_sizes, int n_in,
                              void* d_out, int out_size) {
    const float* x   = (const float*)d_in[0];
    const int*   src = (const int*)  d_in[1];
    const int*   dst = (const int*)  d_in[2];
    const float* ew  = (const float*)d_in[3];
    const float* W1  = (const float*)d_in[4];
    const float* b1  = (const float*)d_in[5];
    const float* W2  = (const float*)d_in[6];
    const float* b2  = (const float*)d_in[7];
    float* out = (float*)d_out;

    int N = in_sizes[0] / 256;
    int E = in_sizes[1];

    float *g, *h1, *xn, *hb1, *hb2;
    __half* xt;
    int* cur;
    int2* edata;
    unsigned *wh1, *wh2;
    cudaGetSymbolAddress((void**)&g,     d_g);
    cudaGetSymbolAddress((void**)&xt,    d_xt);
    cudaGetSymbolAddress((void**)&h1,    d_h1);
    cudaGetSymbolAddress((void**)&xn,    d_xn);
    cudaGetSymbolAddress((void**)&hb1,   d_hb1);
    cudaGetSymbolAddress((void**)&hb2,   d_hb2);
    cudaGetSymbolAddress((void**)&cur,   d_cur);
    cudaGetSymbolAddress((void**)&edata, d_edata);
    cudaGetSymbolAddress((void**)&wh1,   d_wh1);
    cudaGetSymbolAddress((void**)&wh2,   d_wh2);

    int rowBlocks  = (N + 7) / 8;
    int gemmBlocks = (N + BM - 1) / BM;
    int nBlocks256 = (N + 255) / 256;
    int eBlocks256 = (E + 255) / 256;
    int prepBlocks = 2 + (W1_PAIRS + W2_PAIRS + 255) / 256;

    cudaStream_t s1;
    cudaStreamCreateWithFlags(&s1, cudaStreamNonBlocking);
    cudaEvent_t e0, e_csr;
    cudaEventCreateWithFlags(&e0,    cudaEventDisableTiming);
    cudaEventCreateWithFlags(&e_csr, cudaEventDisableTiming);

    // fork
    cudaEventRecord(e0, 0);
    cudaStreamWaitEvent(s1, e0, 0);

    // side stream: scan-free edge bucketing
    zero_cur_kernel<<<nBlocks256, 256, 0, s1>>>(cur, N);
    fill_kernel<<<eBlocks256, 256, 0, s1>>>(src, dst, ew, cur, edata, E);
    cudaEventRecord(e_csr, s1);

    // main stream
    prep_kernel<<<prepBlocks, 256>>>(W1, wh1, W2, wh2, b1, hb1, b2, hb2);
    gemm_mma_kernel<0, 256><<<gemmBlocks, 256>>>(x, wh1, g, xn, N);
    kA_kernel<<<rowBlocks, 256>>>(g, xn, hb1, xt, N);

    cudaStreamWaitEvent(0, e_csr, 0);
    gather_kc_kernel<<<rowBlocks, 256>>>(xt, edata, cur, h1, xn, N);

    // ---- layer 2 ----
    gemm_mma_kernel<1, 64><<<gemmBlocks, 256>>>(h1, wh2, g, nullptr, N);
    kA_kernel<<<rowBlocks, 256>>>(g, xn, hb2, xt, N);
    gather_kc_kernel<<<rowBlocks, 256>>>(xt, edata, cur, out, nullptr, N);

    cudaEventDestroy(e0);
    cudaEventDestroy(e_csr);
    cudaStreamDestroy(s1);
}

// round 16
// speedup vs baseline: 1.2620x; 1.2620x over previous
#include <cuda_runtime.h>
#include <cuda_fp16.h>
#include <cstdint>

// ============================================================================
// HGCN (2-layer hyperbolic GCN), c = 1.
//
// R16 pipeline (= R14 + kA fused into the MMA GEMM epilogue; no d_g buffer):
//   main stream:  prep(W->fp16, hb1, hb2) -> GEMM+kA<0>(x,W1) -> [join csr]
//                 gather1 -> GEMM+kA<1>(h1,W2) -> gather2
//   side stream:  zero_cur -> fill (atomic cursor into dst*MAXDEG buckets)
//
// GEMM: A,W fp16, fp32 accumulate. Epilogue computes the full kA chain
// (mobius_matvec tail + proj + mobius_add(hb) + proj + logmap0) per row via
// smem reduction of ||mx||^2 and mx.hb, then writes xt as fp16 directly.
// xn comes from exact fp32 row norms (MODE 0). Buckets padded to MAXDEG=96.
// ============================================================================

#define BALL_MAXN 0.996f     // (1 - 4e-3)/sqrt(c)
#define EPSN      1e-15f
#define NODES_MAX 80000
#define MAXDEG    96
#define DIM       64

__device__ __half d_xt [NODES_MAX * DIM];
__device__ float  d_h1 [NODES_MAX * DIM];
__device__ float  d_xn [NODES_MAX];
__device__ float  d_hb1[65];
__device__ float  d_hb2[65];
__device__ int    d_cur[NODES_MAX];
__device__ int2   d_edata[(size_t)NODES_MAX * MAXDEG];
__device__ unsigned d_wh1[64 * 256 / 2];   // W1 as packed half2 pairs along K
__device__ unsigned d_wh2[64 * 64 / 2];    // W2 as packed half2 pairs along K

__device__ __forceinline__ float wsum(float v) {
#pragma unroll
    for (int o = 16; o; o >>= 1) v += __shfl_xor_sync(0xffffffffu, v, o);
    return v;
}

__device__ __forceinline__ float artanh_f(float x) {
    x = fminf(fmaxf(x, -1.0f + 1e-7f), 1.0f - 1e-7f);
    return 0.5f * logf((1.0f + x) / (1.0f - x));
}

// pack two fp32 into one half2 (lo half = f0)
__device__ __forceinline__ unsigned pack_h2(float f0, float f1) {
    unsigned h;
    asm("cvt.rn.f16x2.f32 %0, %1, %2;" : "=r"(h) : "f"(f1), "f"(f0));
    return h;
}

#define MMA_FP16(d, a0, a1, a2, a3, b0, b1) \
    asm volatile("mma.sync.aligned.m16n8k16.row.col.f32.f16.f16.f32 " \
        "{%0,%1,%2,%3}, {%4,%5,%6,%7}, {%8,%9}, {%0,%1,%2,%3};" \
        : "+f"((d)[0]), "+f"((d)[1]), "+f"((d)[2]), "+f"((d)[3]) \
        : "r"(a0), "r"(a1), "r"(a2), "r"(a3), "r"(b0), "r"(b1))

// ---------------------------------------------------------------------------
// hb = proj(expmap0(b)); hb[64] = ||hb||^2.  Runs inside a 256-thread block.
// ---------------------------------------------------------------------------
__device__ void hb_dev(const float* __restrict__ b, float* __restrict__ hb) {
    __shared__ float sm[2];
    int t = threadIdx.x;
    float v = (t < 64) ? b[t] : 0.0f;
    float ss = wsum(v * v);
    if (t < 64 && (t & 31) == 0) sm[t >> 5] = ss;
    __syncthreads();
    float tot = sm[0] + sm[1];
    __syncthreads();
    float nr = sqrtf(tot);
    float n  = fmaxf(nr, EPSN);
    float tn = tanhf(n);
    float e  = v * (tn / n);
    float en = fmaxf(tn * (nr / n), EPSN);
    float cf = (en > BALL_MAXN) ? (BALL_MAXN / en) : 1.0f;
    e *= cf;
    if (t < 64) hb[t] = e;
    float ss2 = wsum((t < 64) ? e * e : 0.0f);
    if (t < 64 && (t & 31) == 0) sm[t >> 5] = ss2;
    __syncthreads();
    if (t == 0) hb[64] = sm[0] + sm[1];
}

// ---------------------------------------------------------------------------
// prep: block 0 -> hb1, block 1 -> hb2, blocks 2.. -> W1/W2 fp16 pack.
// ---------------------------------------------------------------------------
#define W1_PAIRS (64 * 256 / 2)
#define W2_PAIRS (64 * 64 / 2)

__global__ void prep_kernel(const float* __restrict__ W1, unsigned* __restrict__ wh1,
                            const float* __restrict__ W2, unsigned* __restrict__ wh2,
                            const float* __restrict__ b1, float* __restrict__ hb1,
                            const float* __restrict__ b2, float* __restrict__ hb2) {
    int blk = blockIdx.x;
    if (blk == 0) { hb_dev(b1, hb1); return; }
    if (blk == 1) { hb_dev(b2, hb2); return; }
    int i = (blk - 2) * 256 + threadIdx.x;
    if (i < W1_PAIRS) {
        float2 f = ((const float2*)W1)[i];
        wh1[i] = pack_h2(f.x, f.y);
    } else if (i < W1_PAIRS + W2_PAIRS) {
        int j = i - W1_PAIRS;
        float2 f = ((const float2*)W2)[j];
        wh2[j] = pack_h2(f.x, f.y);
    }
}

// ---------------------------------------------------------------------------
// Scan-free CSR: zero cursors, then bucket-fill edata[dst*MAXDEG + pos].
// ---------------------------------------------------------------------------
__global__ void zero_cur_kernel(int* __restrict__ cur, int N) {
    int i = blockIdx.x * blockDim.x + threadIdx.x;
    if (i < N) cur[i] = 0;
}

__global__ void fill_kernel(const int* __restrict__ src, const int* __restrict__ dst,
                            const float* __restrict__ w, int* __restrict__ cur,
                            int2* __restrict__ ed, int E) {
    int e = blockIdx.x * blockDim.x + threadIdx.x;
    if (e >= E) return;
    int d = dst[e];
    int pos = atomicAdd(&cur[d], 1);
    if (pos < MAXDEG)
        ed[(size_t)d * MAXDEG + pos] = make_int2(src[e], __float_as_int(w[e]));
}

// ---------------------------------------------------------------------------
// Fused fp16 MMA GEMM + kA: xt[N,64] (fp16) from A[N,K], W fp16, hb.
// Tile M=128, N=64, BK=32; 8 warps 4(m) x 2(n); 2 mt x 4 nt per warp.
// Register prefetch + double-buffered smem.
// Epilogue: smem-reduce ||mx||^2, mx.hb per row -> kA scalars -> fp16 store.
// MODE 0: encode scale (exact fp32 row norms) folded in; writes xn.
// ---------------------------------------------------------------------------
#define BM 128
#define KPAD 17

template <int MODE, int K>
__global__ __launch_bounds__(256, 2)
void gemm_ka_kernel(const float* __restrict__ A,
                    const unsigned* __restrict__ wh,
                    const float* __restrict__ hb,
                    __half* __restrict__ xt, float* __restrict__ xn_io, int N) {
    __shared__ unsigned Ah[2][BM * KPAD];
    __shared__ float sred[4 * 256];
    __shared__ float sp1[BM * 9];
    __shared__ float sp2[BM * 9];
    __shared__ float sA[BM];
    __shared__ float sB[BM];
    __shared__ float hbs[65];

    int tid  = threadIdx.x;
    int lane = tid & 31;
    int wid  = tid >> 5;
    int warp_m = wid >> 1;
    int warp_n = wid & 1;
    int block_row = blockIdx.x * BM;

    int qrow = lane >> 2;
    int qcol = lane & 3;

    if (tid < 65) hbs[tid] = hb[tid];

    float acc[2][4][4];
#pragma unroll
    for (int mt = 0; mt < 2; mt++)
#pragma unroll
        for (int nt = 0; nt < 4; nt++)
#pragma unroll
            for (int r = 0; r < 4; r++) acc[mt][nt][r] = 0.0f;

    float ssl[4] = {0.f, 0.f, 0.f, 0.f};

    int rr[4], kb[4];
    const float* aptr[4];
#pragma unroll
    for (int i = 0; i < 4; i++) {
        int idx = tid + i * 256;
        rr[i] = idx >> 3;
        kb[i] = ((idx & 7) << 2) >> 1;
        int gr = block_row + rr[i];
        if (gr >= N) gr = N - 1;
        aptr[i] = A + (size_t)gr * K + ((idx & 7) << 2);
    }

    float4 rv[4];
#pragma unroll
    for (int i = 0; i < 4; i++) rv[i] = *(const float4*)(aptr[i]);

    const int S = K / 32;
#pragma unroll 1
    for (int s = 0; s < S; s++) {
        int buf = s & 1;
#pragma unroll
        for (int i = 0; i < 4; i++) {
            int base = rr[i] * KPAD + kb[i];
            Ah[buf][base]     = pack_h2(rv[i].x, rv[i].y);
            Ah[buf][base + 1] = pack_h2(rv[i].z, rv[i].w);
            if (MODE == 0)
                ssl[i] += rv[i].x * rv[i].x + rv[i].y * rv[i].y
                        + rv[i].z * rv[i].z + rv[i].w * rv[i].w;
        }
        __syncthreads();

        if (s + 1 < S) {
#pragma unroll
            for (int i = 0; i < 4; i++)
                rv[i] = *(const float4*)(aptr[i] + (s + 1) * 32);
        }

#pragma unroll
        for (int kc = 0; kc < 2; kc++) {
            int pc = kc * 8 + qcol;
            unsigned ah[2][4];
#pragma unroll
            for (int mt = 0; mt < 2; mt++) {
                int r0 = warp_m * 32 + mt * 16 + qrow;
                ah[mt][0] = Ah[buf][r0 * KPAD + pc];
                ah[mt][1] = Ah[buf][(r0 + 8) * KPAD + pc];
                ah[mt][2] = Ah[buf][r0 * KPAD + pc + 4];
                ah[mt][3] = Ah[buf][(r0 + 8) * KPAD + pc + 4];
            }
#pragma unroll
            for (int nt = 0; nt < 4; nt++) {
                int n  = warp_n * 32 + nt * 8 + qrow;
                int kp = (s * 32 + kc * 16) / 2 + qcol;
                int bidx = n * (K / 2) + kp;
                unsigned b0 = __ldg(&wh[bidx]);
                unsigned b1 = __ldg(&wh[bidx + 4]);
#pragma unroll
                for (int mt = 0; mt < 2; mt++)
                    MMA_FP16(acc[mt][nt], ah[mt][0], ah[mt][1], ah[mt][2], ah[mt][3], b0, b1);
            }
        }
    }

    // ---- partial sums for kA: raw ||mx||^2 and mx.hb per row ----
    int part = warp_n * 4 + qcol;                 // 0..7
#pragma unroll
    for (int mt = 0; mt < 2; mt++) {
#pragma unroll
        for (int rp = 0; rp < 2; rp++) {
            int r = warp_m * 32 + mt * 16 + rp * 8 + qrow;
            float p1 = 0.0f, p2 = 0.0f;
#pragma unroll
            for (int nt = 0; nt < 4; nt++) {
                int c = warp_n * 32 + nt * 8 + qcol * 2;
                float m0 = acc[mt][nt][rp * 2 + 0];
                float m1 = acc[mt][nt][rp * 2 + 1];
                p1 += m0 * m0 + m1 * m1;
                p2 += m0 * hbs[c] + m1 * hbs[c + 1];
            }
            sp1[r * 9 + part] = p1;
            sp2[r * 9 + part] = p2;
        }
    }
    if (MODE == 0) {
        sred[0 * 256 + tid] = ssl[0];
        sred[1 * 256 + tid] = ssl[1];
        sred[2 * 256 + tid] = ssl[2];
        sred[3 * 256 + tid] = ssl[3];
    }
    __syncthreads();

    // ---- per-row scalar chain ----
    if (tid < BM) {
        int r  = tid;
        int gr = block_row + r;
        int grc = (gr < N) ? gr : (N - 1);

        float sc = 1.0f;
        float xn;
        if (MODE == 0) {
            int grp = r >> 5;
            int t0  = (r & 31) << 3;
            float s2 = 0.0f;
#pragma unroll
            for (int j = 0; j < 8; j++) s2 += sred[grp * 256 + t0 + j];
            float nxr = sqrtf(s2);
            float nx  = fmaxf(nxr, EPSN);
            float t   = tanhf(nx);
            float en  = fmaxf(t * (nxr / nx), EPSN);
            float cf  = (en > BALL_MAXN) ? (BALL_MAXN / en) : 1.0f;
            sc = (t / nx) * cf;
            xn = fmaxf(en * cf, EPSN);
            if (gr < N) xn_io[gr] = xn;
        } else {
            xn = xn_io[grc];
        }

        float S1 = 0.0f, S2 = 0.0f;
#pragma unroll
        for (int j = 0; j < 8; j++) {
            S1 += sp1[r * 9 + j];
            S2 += sp2[r * 9 + j];
        }
        float mxn2 = sc * sc * S1;       // ||mx||^2 with encode scale
        float mxy  = sc * S2;            // mx . hb

        float mxnr = sqrtf(mxn2);
        float mxn  = fmaxf(mxnr, EPSN);
        float tv   = tanhf(mxn / xn * artanh_f(xn));
        float rs   = tv / mxn;
        float rn   = fmaxf(mxnr * fabsf(rs), EPSN);
        float f    = (rn > BALL_MAXN) ? (BALL_MAXN / rn) : 1.0f;
        float rsf  = rs * f;

        float y2  = hbs[64];
        float x2  = mxn2 * rsf * rsf;
        float xy  = mxy * rsf;
        float den = fmaxf(1.0f + 2.0f * xy + x2 * y2, EPSN);
        float ca  = (1.0f + 2.0f * xy + y2) / den;
        float cb  = (1.0f - x2) / den;

        float hn2 = ca * ca * x2 + 2.0f * ca * cb * xy + cb * cb * y2;
        float hnr = sqrtf(hn2);
        float hn  = fmaxf(hnr, EPSN);
        float cf2 = (hn > BALL_MAXN) ? (BALL_MAXN / hn) : 1.0f;
        float hna = fmaxf(hnr * cf2, EPSN);
        float lc  = artanh_f(hna) / hna;

        sA[r] = lc * cf2 * ca * rsf * sc;   // multiplies raw acc
        sB[r] = lc * cf2 * cb;              // multiplies hb
    }
    __syncthreads();

    // ---- write xt = Ar*acc + Br*hb as fp16 ----
#pragma unroll
    for (int mt = 0; mt < 2; mt++) {
#pragma unroll
        for (int rp = 0; rp < 2; rp++) {
            int r  = warp_m * 32 + mt * 16 + rp * 8 + qrow;
            int gr = block_row + r;
            if (gr >= N) continue;
            float Ar = sA[r], Br = sB[r];
#pragma unroll
            for (int nt = 0; nt < 4; nt++) {
                int c = warp_n * 32 + nt * 8 + qcol * 2;
                float o0 = Ar * acc[mt][nt][rp * 2 + 0] + Br * hbs[c];
                float o1 = Ar * acc[mt][nt][rp * 2 + 1] + Br * hbs[c + 1];
                *(__half2*)(xt + (size_t)gr * DIM + c) = __floats2half2_rn(o0, o1);
            }
        }
    }
}

// ---------------------------------------------------------------------------
// Gather + kC over padded buckets (R14 form).
// ---------------------------------------------------------------------------
__global__ void gather_kc_kernel(const __half* __restrict__ xt,
                                 const int2* __restrict__ ed,
                                 const int* __restrict__ deg,
                                 float* __restrict__ out,
                                 float* __restrict__ xn_out, int N) {
    int row  = blockIdx.x * 8 + (threadIdx.x >> 5);
    int lane = threadIdx.x & 31;
    if (row >= N) return;

    size_t beg = (size_t)row * MAXDEG;
    int dc = min(deg[row], MAXDEG);

    float ax = 0.0f, ay = 0.0f;
    for (int i0 = 0; i0 < dc; i0 += 32) {
        int i = i0 + lane;
        int2 e = (i < dc) ? __ldg(&ed[beg + i]) : make_int2(0, 0);
        int cnt = min(32, dc - i0);
        for (int j = 0; j < cnt; j++) {
            int   s  = __shfl_sync(0xffffffffu, e.x, j);
            float wt = __int_as_float(__shfl_sync(0xffffffffu, e.y, j));
            __half2 v = *(const __half2*)(xt + (size_t)s * DIM + lane * 2);
            float2 f = __half22float2(v);
            ax = fmaf(wt, f.x, ax);
            ay = fmaf(wt, f.y, ay);
        }
    }

    float na2 = wsum(ax * ax + ay * ay);
    float nar = sqrtf(na2);
    float na  = fmaxf(nar, EPSN);
    float t   = tanhf(na);
    float f1  = t / na;
    float en  = fmaxf(t * (nar / na), EPSN);
    float c1  = (en > BALL_MAXN) ? (BALL_MAXN / en) : 1.0f;
    float hn  = fmaxf(en * c1, EPSN);
    float lco = artanh_f(hn) / hn * (f1 * c1);

    float lx = fmaxf(ax * lco, 0.0f);
    float ly = fmaxf(ay * lco, 0.0f);

    float nx2 = wsum(lx * lx + ly * ly);
    float nxr = sqrtf(nx2);
    float nx  = fmaxf(nxr, EPSN);
    float t2  = tanhf(nx);
    float f2  = t2 / nx;
    float en2 = fmaxf(t2 * (nxr / nx), EPSN);
    float c2  = (en2 > BALL_MAXN) ? (BALL_MAXN / en2) : 1.0f;

    float2 o = make_float2(lx * (f2 * c2), ly * (f2 * c2));
    *(float2*)(out + (size_t)row * DIM + lane * 2) = o;

    if (xn_out != nullptr && lane == 0)
        xn_out[row] = fmaxf(en2 * c2, EPSN);
}

// ---------------------------------------------------------------------------
// Launch
// ---------------------------------------------------------------------------
extern "C" void kernel_launch(void* const* d_in, const int* in_sizes, int n_in,
                              void* d_out, int out_size) {
    const float* x   = (const float*)d_in[0];
    const int*   src = (const int*)  d_in[1];
    const int*   dst = (const int*)  d_in[2];
    const float* ew  = (const float*)d_in[3];
    const float* W1  = (const float*)d_in[4];
    const float* b1  = (const float*)d_in[5];
    const float* W2  = (const float*)d_in[6];
    const float* b2  = (const float*)d_in[7];
    float* out = (float*)d_out;

    int N = in_sizes[0] / 256;
    int E = in_sizes[1];

    float *h1, *xn, *hb1, *hb2;
    __half* xt;
    int* cur;
    int2* edata;
    unsigned *wh1, *wh2;
    cudaGetSymbolAddress((void**)&xt,    d_xt);
    cudaGetSymbolAddress((void**)&h1,    d_h1);
    cudaGetSymbolAddress((void**)&xn,    d_xn);
    cudaGetSymbolAddress((void**)&hb1,   d_hb1);
    cudaGetSymbolAddress((void**)&hb2,   d_hb2);
    cudaGetSymbolAddress((void**)&cur,   d_cur);
    cudaGetSymbolAddress((void**)&edata, d_edata);
    cudaGetSymbolAddress((void**)&wh1,   d_wh1);
    cudaGetSymbolAddress((void**)&wh2,   d_wh2);

    int rowBlocks  = (N + 7) / 8;
    int gemmBlocks = (N + BM - 1) / BM;
    int nBlocks256 = (N + 255) / 256;
    int eBlocks256 = (E + 255) / 256;
    int prepBlocks = 2 + (W1_PAIRS + W2_PAIRS + 255) / 256;

    cudaStream_t s1;
    cudaStreamCreateWithFlags(&s1, cudaStreamNonBlocking);
    cudaEvent_t e0, e_csr;
    cudaEventCreateWithFlags(&e0,    cudaEventDisableTiming);
    cudaEventCreateWithFlags(&e_csr, cudaEventDisableTiming);

    // fork
    cudaEventRecord(e0, 0);
    cudaStreamWaitEvent(s1, e0, 0);

    // side stream: scan-free edge bucketing
    zero_cur_kernel<<<nBlocks256, 256, 0, s1>>>(cur, N);
    fill_kernel<<<eBlocks256, 256, 0, s1>>>(src, dst, ew, cur, edata, E);
    cudaEventRecord(e_csr, s1);

    // main stream
    prep_kernel<<<prepBlocks, 256>>>(W1, wh1, W2, wh2, b1, hb1, b2, hb2);
    gemm_ka_kernel<0, 256><<<gemmBlocks, 256>>>(x, wh1, hb1, xt, xn, N);

    cudaStreamWaitEvent(0, e_csr, 0);
    gather_kc_kernel<<<rowBlocks, 256>>>(xt, edata, cur, h1, xn, N);

    // ---- layer 2 ----
    gemm_ka_kernel<1, 64><<<gemmBlocks, 256>>>(h1, wh2, hb2, xt, xn, N);
    gather_kc_kernel<<<rowBlocks, 256>>>(xt, edata, cur, out, nullptr, N);

    cudaEventDestroy(e0);
    cudaEventDestroy(e_csr);
    cudaStreamDestroy(s1);
}